// round 2
// baseline (speedup 1.0000x reference)
#include <cuda_runtime.h>
#include <math.h>

#define SEQ    2048
#define BATCH  2
#define MTOK   4096      // BATCH*SEQ
#define DM     1024
#define NH     16
#define DHEAD  64
#define NEGV   -1000000000.0f

// -------- scratch (device globals; no allocation allowed) --------
__device__ float g_xln[MTOK * DM];
__device__ float g_qb [MTOK * DM];
__device__ float g_kb [MTOK * DM];
__device__ float g_vb [MTOK * DM];
__device__ float g_ab [MTOK * DM];
__device__ float g_hb [MTOK * DM];
__device__ float g_rb [MTOK * DM];
__device__ float g_zb [MTOK * DM];
__device__ float g_tb [MTOK * 4 * DM];

// -------- helpers --------
__device__ __forceinline__ float block_sum(float v, float* red) {
    int lane = threadIdx.x & 31, w = threadIdx.x >> 5;
    #pragma unroll
    for (int o = 16; o > 0; o >>= 1) v += __shfl_xor_sync(0xffffffffu, v, o);
    __syncthreads();               // protect red[] reuse across calls
    if (lane == 0) red[w] = v;
    __syncthreads();
    if (w == 0) {
        float x = (lane < 8) ? red[lane] : 0.0f;
        #pragma unroll
        for (int o = 4; o > 0; o >>= 1) x += __shfl_xor_sync(0xffffffffu, x, o);
        if (lane == 0) red[0] = x;
    }
    __syncthreads();
    return red[0];
}

__device__ __forceinline__ float gelu_exact(float x) {
    return 0.5f * x * (1.0f + erff(x * 0.7071067811865475f));
}

// -------- fused embedding + LN1 --------
// x = tok_emb[target_ids] + pos_emb[s]; out = LN(x)*g + b
__global__ __launch_bounds__(256) void embed_ln_kernel(
    const int* __restrict__ ids, const float* __restrict__ tok,
    const float* __restrict__ pos, const float* __restrict__ gw,
    const float* __restrict__ bw, float* __restrict__ out)
{
    __shared__ float red[32];
    int row = blockIdx.x;                 // 0..4095
    int s   = row & (SEQ - 1);
    int id  = ids[row];
    int d   = threadIdx.x * 4;
    float4 t4 = *(const float4*)(tok + (size_t)id * DM + d);
    float4 p4 = *(const float4*)(pos + (size_t)s  * DM + d);
    float4 v;
    v.x = t4.x + p4.x; v.y = t4.y + p4.y; v.z = t4.z + p4.z; v.w = t4.w + p4.w;
    float mu = block_sum(v.x + v.y + v.z + v.w, red) * (1.0f / DM);
    float dx = v.x - mu, dy = v.y - mu, dz = v.z - mu, dw = v.w - mu;
    float var = block_sum(dx*dx + dy*dy + dz*dz + dw*dw, red) * (1.0f / DM);
    float rstd = rsqrtf(var + 1e-5f);
    float4 o;
    o.x = dx * rstd * gw[d+0] + bw[d+0];
    o.y = dy * rstd * gw[d+1] + bw[d+1];
    o.z = dz * rstd * gw[d+2] + bw[d+2];
    o.w = dw * rstd * gw[d+3] + bw[d+3];
    *(float4*)(out + (size_t)row * DM + d) = o;
}

// -------- plain LN --------
__global__ __launch_bounds__(256) void ln_kernel(
    const float* __restrict__ in, const float* __restrict__ gw,
    const float* __restrict__ bw, float* __restrict__ out)
{
    __shared__ float red[32];
    int row = blockIdx.x;
    int d   = threadIdx.x * 4;
    float4 v = *(const float4*)(in + (size_t)row * DM + d);
    float mu = block_sum(v.x + v.y + v.z + v.w, red) * (1.0f / DM);
    float dx = v.x - mu, dy = v.y - mu, dz = v.z - mu, dw = v.w - mu;
    float var = block_sum(dx*dx + dy*dy + dz*dz + dw*dw, red) * (1.0f / DM);
    float rstd = rsqrtf(var + 1e-5f);
    float4 o;
    o.x = dx * rstd * gw[d+0] + bw[d+0];
    o.y = dy * rstd * gw[d+1] + bw[d+1];
    o.z = dz * rstd * gw[d+2] + bw[d+2];
    o.w = dw * rstd * gw[d+3] + bw[d+3];
    *(float4*)(out + (size_t)row * DM + d) = o;
}

// -------- tiled SGEMM: C = A[M,K] * W[K,N] + bias, epilogue --------
// epi: 0 = none, 1 = exact GELU, 2 = add residual R
__global__ __launch_bounds__(256) void gemm_kernel(
    const float* __restrict__ A, const float* __restrict__ W,
    const float* __restrict__ bias, const float* __restrict__ R,
    float* __restrict__ C, int M, int N, int K, int epi)
{
    __shared__ float As[16][128];   // k-major (transposed A tile)
    __shared__ float Bs[16][64];
    const int tid = threadIdx.x;
    const int tx = tid & 15, ty = tid >> 4;
    const int m0 = blockIdx.y * 128, n0 = blockIdx.x * 64;
    const int arow = tid >> 1, ak = (tid & 1) * 8;

    float acc[8][4];
    #pragma unroll
    for (int i = 0; i < 8; i++)
        #pragma unroll
        for (int j = 0; j < 4; j++) acc[i][j] = 0.0f;

    for (int k0 = 0; k0 < K; k0 += 16) {
        const float* ap = A + (size_t)(m0 + arow) * K + k0 + ak;
        float4 a0 = *(const float4*)ap;
        float4 a1 = *(const float4*)(ap + 4);
        As[ak+0][arow] = a0.x; As[ak+1][arow] = a0.y;
        As[ak+2][arow] = a0.z; As[ak+3][arow] = a0.w;
        As[ak+4][arow] = a1.x; As[ak+5][arow] = a1.y;
        As[ak+6][arow] = a1.z; As[ak+7][arow] = a1.w;
        *(float4*)&Bs[ty][tx * 4] =
            *(const float4*)(W + (size_t)(k0 + ty) * N + n0 + tx * 4);
        __syncthreads();
        #pragma unroll
        for (int kk = 0; kk < 16; kk++) {
            float4 b4 = *(float4*)&Bs[kk][tx << 2];
            float4 x0 = *(float4*)&As[kk][ty << 3];
            float4 x1 = *(float4*)&As[kk][(ty << 3) + 4];
            float ax[8] = {x0.x, x0.y, x0.z, x0.w, x1.x, x1.y, x1.z, x1.w};
            float bx[4] = {b4.x, b4.y, b4.z, b4.w};
            #pragma unroll
            for (int i = 0; i < 8; i++)
                #pragma unroll
                for (int j = 0; j < 4; j++) acc[i][j] += ax[i] * bx[j];
        }
        __syncthreads();
    }

    float bj[4];
    #pragma unroll
    for (int j = 0; j < 4; j++) bj[j] = bias[n0 + tx * 4 + j];

    #pragma unroll
    for (int i = 0; i < 8; i++) {
        size_t off = (size_t)(m0 + ty * 8 + i) * N + n0 + tx * 4;
        float4 c;
        c.x = acc[i][0] + bj[0]; c.y = acc[i][1] + bj[1];
        c.z = acc[i][2] + bj[2]; c.w = acc[i][3] + bj[3];
        if (epi == 1) {
            c.x = gelu_exact(c.x); c.y = gelu_exact(c.y);
            c.z = gelu_exact(c.z); c.w = gelu_exact(c.w);
        } else if (epi == 2) {
            float4 r4 = *(const float4*)(R + off);
            c.x += r4.x; c.y += r4.y; c.z += r4.z; c.w += r4.w;
        }
        *(float4*)(C + off) = c;
    }
}

// -------- flash attention (fp32, BQ=BK=64, online softmax) --------
// Q/K/V layout: [b, s, h, d] i.e. [(b*S+s)*DM + h*64 + d].  O same layout.
// Masks replicated as fp32 ADDITIONS of -1e9 (matches reference rounding).
__global__ __launch_bounds__(256) void flash_kernel(
    const float* __restrict__ Qg, const float* __restrict__ Kg,
    const float* __restrict__ Vg, const int* __restrict__ ids,
    float* __restrict__ Og, int causal)
{
    extern __shared__ float sm[];
    float* Qs = sm;                 // [d][q]  64x64
    float* Ks = sm + 4096;          // [d][c]  64x64
    float* Vs = sm + 8192;          // [k][d]  64x64
    float* Ps = sm + 12288;         // [q][65] padded
    int*   sid = (int*)(sm + 12288 + 64 * 65);

    const int tid = threadIdx.x;
    const int tx = tid & 15, ty = tid >> 4;
    const int qt = blockIdx.x, h = blockIdx.y, b = blockIdx.z;
    const int qbase = qt * 64;
    const float* Qp = Qg + (size_t)b * SEQ * DM + h * DHEAD;
    const float* Kp = Kg + (size_t)b * SEQ * DM + h * DHEAD;
    const float* Vp = Vg + (size_t)b * SEQ * DM + h * DHEAD;

    // load Q tile transposed (dim-major)
    {
        int r = tid >> 2, dseg = (tid & 3) * 16;
        const float* gp = Qp + (size_t)(qbase + r) * DM + dseg;
        #pragma unroll
        for (int u = 0; u < 4; u++) {
            float4 q4 = *(const float4*)(gp + u * 4);
            Qs[(dseg + u*4 + 0) * 64 + r] = q4.x;
            Qs[(dseg + u*4 + 1) * 64 + r] = q4.y;
            Qs[(dseg + u*4 + 2) * 64 + r] = q4.z;
            Qs[(dseg + u*4 + 3) * 64 + r] = q4.w;
        }
    }

    float m[4], l[4], acc[4][4];
    #pragma unroll
    for (int i = 0; i < 4; i++) {
        m[i] = -3.0e38f; l[i] = 0.0f;
        #pragma unroll
        for (int j = 0; j < 4; j++) acc[i][j] = 0.0f;
    }

    const int nkt = causal ? (qt + 1) : (SEQ / 64);
    for (int kt = 0; kt < nkt; kt++) {
        const int kbase = kt * 64;
        {
            int r = tid >> 2, dseg = (tid & 3) * 16;
            const float* kp = Kp + (size_t)(kbase + r) * DM + dseg;
            const float* vp = Vp + (size_t)(kbase + r) * DM + dseg;
            #pragma unroll
            for (int u = 0; u < 4; u++) {
                float4 k4 = *(const float4*)(kp + u * 4);
                Ks[(dseg + u*4 + 0) * 64 + r] = k4.x;
                Ks[(dseg + u*4 + 1) * 64 + r] = k4.y;
                Ks[(dseg + u*4 + 2) * 64 + r] = k4.z;
                Ks[(dseg + u*4 + 3) * 64 + r] = k4.w;
                *(float4*)&Vs[r * 64 + dseg + u * 4] = *(const float4*)(vp + u * 4);
            }
            if (tid < 64) sid[tid] = ids[b * SEQ + kbase + tid];
        }
        __syncthreads();

        // scores: 64x64 = Q^T tile dot K tile
        float sc[4][4];
        #pragma unroll
        for (int i = 0; i < 4; i++)
            #pragma unroll
            for (int j = 0; j < 4; j++) sc[i][j] = 0.0f;
        #pragma unroll 8
        for (int d = 0; d < 64; d++) {
            float4 q4 = *(float4*)&Qs[d * 64 + ty * 4];
            float4 k4 = *(float4*)&Ks[d * 64 + tx * 4];
            float qa[4] = {q4.x, q4.y, q4.z, q4.w};
            float ka[4] = {k4.x, k4.y, k4.z, k4.w};
            #pragma unroll
            for (int i = 0; i < 4; i++)
                #pragma unroll
                for (int j = 0; j < 4; j++) sc[i][j] += qa[i] * ka[j];
        }

        // scale + masks + online softmax
        #pragma unroll
        for (int i = 0; i < 4; i++) {
            int qrow = qbase + ty * 4 + i;
            float rowmax = -3.0e38f;
            #pragma unroll
            for (int j = 0; j < 4; j++) {
                float v = sc[i][j] * 0.125f;       // 1/sqrt(64)
                int kc = kbase + tx * 4 + j;
                if (causal && kc > qrow) v += NEGV;
                if (sid[tx * 4 + j] == 0) v += NEGV;
                sc[i][j] = v;
                rowmax = fmaxf(rowmax, v);
            }
            #pragma unroll
            for (int o = 8; o > 0; o >>= 1)
                rowmax = fmaxf(rowmax, __shfl_xor_sync(0xffffffffu, rowmax, o));
            float mnew  = fmaxf(m[i], rowmax);
            float alpha = __expf(m[i] - mnew);
            float rs = 0.0f;
            #pragma unroll
            for (int j = 0; j < 4; j++) {
                float p = __expf(sc[i][j] - mnew);
                Ps[(ty * 4 + i) * 65 + tx * 4 + j] = p;
                rs += p;
            }
            #pragma unroll
            for (int o = 8; o > 0; o >>= 1)
                rs += __shfl_xor_sync(0xffffffffu, rs, o);
            l[i] = l[i] * alpha + rs;
            m[i] = mnew;
            #pragma unroll
            for (int j = 0; j < 4; j++) acc[i][j] *= alpha;
        }
        __syncthreads();

        // acc += P @ V
        #pragma unroll 4
        for (int kk = 0; kk < 64; kk++) {
            float4 v4 = *(float4*)&Vs[kk * 64 + tx * 4];
            #pragma unroll
            for (int i = 0; i < 4; i++) {
                float p = Ps[(ty * 4 + i) * 65 + kk];
                acc[i][0] += p * v4.x; acc[i][1] += p * v4.y;
                acc[i][2] += p * v4.z; acc[i][3] += p * v4.w;
            }
        }
        __syncthreads();
    }

    #pragma unroll
    for (int i = 0; i < 4; i++) {
        float inv = 1.0f / l[i];
        float4 o;
        o.x = acc[i][0] * inv; o.y = acc[i][1] * inv;
        o.z = acc[i][2] * inv; o.w = acc[i][3] * inv;
        size_t off = ((size_t)b * SEQ + qbase + ty * 4 + i) * DM + h * DHEAD + tx * 4;
        *(float4*)(Og + off) = o;
    }
}

// -------- host pipeline --------
extern "C" void kernel_launch(void* const* d_in, const int* in_sizes, int n_in,
                              void* d_out, int out_size)
{
    const float* input_embedding = (const float*)d_in[0];
    const int*   input_ids       = (const int*)  d_in[1];
    const int*   target_ids      = (const int*)  d_in[2];
    const float* tok_emb = (const float*)d_in[3];
    const float* pos_emb = (const float*)d_in[4];
    const float* ln1_g = (const float*)d_in[5],  *ln1_b = (const float*)d_in[6];
    const float* q1_w  = (const float*)d_in[7],  *q1_b  = (const float*)d_in[8];
    const float* k1_w  = (const float*)d_in[9],  *k1_b  = (const float*)d_in[10];
    const float* v1_w  = (const float*)d_in[11], *v1_b  = (const float*)d_in[12];
    const float* out1_w= (const float*)d_in[13], *out1_b= (const float*)d_in[14];
    const float* ln2_g = (const float*)d_in[15], *ln2_b = (const float*)d_in[16];
    const float* q2_w  = (const float*)d_in[17], *q2_b  = (const float*)d_in[18];
    const float* k2_w  = (const float*)d_in[19], *k2_b  = (const float*)d_in[20];
    const float* v2_w  = (const float*)d_in[21], *v2_b  = (const float*)d_in[22];
    const float* out2_w= (const float*)d_in[23], *out2_b= (const float*)d_in[24];
    const float* ln3_g = (const float*)d_in[25], *ln3_b = (const float*)d_in[26];
    const float* mlp_w1= (const float*)d_in[27], *mlp_b1= (const float*)d_in[28];
    const float* mlp_w2= (const float*)d_in[29], *mlp_b2= (const float*)d_in[30];

    float *xln, *qb, *kb, *vb, *ab, *hb, *rb, *zb, *tb;
    cudaGetSymbolAddress((void**)&xln, g_xln);
    cudaGetSymbolAddress((void**)&qb,  g_qb);
    cudaGetSymbolAddress((void**)&kb,  g_kb);
    cudaGetSymbolAddress((void**)&vb,  g_vb);
    cudaGetSymbolAddress((void**)&ab,  g_ab);
    cudaGetSymbolAddress((void**)&hb,  g_hb);
    cudaGetSymbolAddress((void**)&rb,  g_rb);
    cudaGetSymbolAddress((void**)&zb,  g_zb);
    cudaGetSymbolAddress((void**)&tb,  g_tb);

    const int FLASH_SMEM = (4096 * 3 + 64 * 65) * 4 + 64 * 4;   // 66048 B
    cudaFuncSetAttribute(flash_kernel,
                         cudaFuncAttributeMaxDynamicSharedMemorySize, FLASH_SMEM);

    dim3 gN1(DM / 64, MTOK / 128);          // N=1024
    dim3 gN4(4 * DM / 64, MTOK / 128);      // N=4096
    dim3 gF(SEQ / 64, NH, BATCH);

    // x = LN1(tok_emb[tgt] + pos)
    embed_ln_kernel<<<MTOK, 256>>>(target_ids, tok_emb, pos_emb, ln1_g, ln1_b, xln);

    // self-attention
    gemm_kernel<<<gN1, 256>>>(xln, q1_w, q1_b, nullptr, qb, MTOK, DM, DM, 0);
    gemm_kernel<<<gN1, 256>>>(xln, k1_w, k1_b, nullptr, kb, MTOK, DM, DM, 0);
    gemm_kernel<<<gN1, 256>>>(xln, v1_w, v1_b, nullptr, vb, MTOK, DM, DM, 0);
    flash_kernel<<<gF, 256, FLASH_SMEM>>>(qb, kb, vb, target_ids, ab, 1);
    gemm_kernel<<<gN1, 256>>>(ab, out1_w, out1_b, xln, hb, MTOK, DM, DM, 2); // h = xln + attn

    // cross-attention (NOTE: reference overwrites h with LN2(h); residual uses LN2 output)
    ln_kernel<<<MTOK, 256>>>(hb, ln2_g, ln2_b, zb);                          // h2 = LN2(h)
    gemm_kernel<<<gN1, 256>>>(zb, q2_w, q2_b, nullptr, qb, MTOK, DM, DM, 0);
    gemm_kernel<<<gN1, 256>>>(input_embedding, k2_w, k2_b, nullptr, kb, MTOK, DM, DM, 0);
    gemm_kernel<<<gN1, 256>>>(input_embedding, v2_w, v2_b, nullptr, vb, MTOK, DM, DM, 0);
    flash_kernel<<<gF, 256, FLASH_SMEM>>>(qb, kb, vb, input_ids, ab, 0);
    gemm_kernel<<<gN1, 256>>>(ab, out2_w, out2_b, zb, rb, MTOK, DM, DM, 2);  // r = cross + LN2(h)

    // MLP
    ln_kernel<<<MTOK, 256>>>(rb, ln3_g, ln3_b, zb);                          // z
    gemm_kernel<<<gN4, 256>>>(zb, mlp_w1, mlp_b1, nullptr, tb, MTOK, 4 * DM, DM, 1);      // GELU
    gemm_kernel<<<gN1, 256>>>(tb, mlp_w2, mlp_b2, rb, (float*)d_out, MTOK, DM, 4 * DM, 2); // + r
}

// round 4
// speedup vs baseline: 1.5743x; 1.5743x over previous
#include <cuda_runtime.h>
#include <cuda_bf16.h>
#include <math.h>
#include <stdint.h>

#define SEQ    2048
#define BATCH  2
#define MTOK   4096      // BATCH*SEQ
#define DM     1024
#define NH     16
#define DHEAD  64
#define NEGV   -1000000000.0f

// -------- scratch (device globals; no allocation allowed) --------
__device__ float g_xln[MTOK * DM];
__device__ float g_qb [MTOK * DM];
__device__ float g_kb [MTOK * DM];
__device__ float g_vb [MTOK * DM];
__device__ float g_ab [MTOK * DM];
__device__ float g_hb [MTOK * DM];
__device__ float g_rb [MTOK * DM];
__device__ float g_zb [MTOK * DM];
__device__ float g_tb [MTOK * 4 * DM];
__device__ float g_wt [16 * 1024 * 1024];   // transposed weights [N][K]

#define WT_Q1   (0u)
#define WT_K1   (1u << 20)
#define WT_V1   (2u << 20)
#define WT_O1   (3u << 20)
#define WT_Q2   (4u << 20)
#define WT_K2   (5u << 20)
#define WT_V2   (6u << 20)
#define WT_O2   (7u << 20)
#define WT_M1   (8u << 20)   // [4096][1024]
#define WT_M2   (12u << 20)  // [1024][4096]

// ============================================================
// helpers
// ============================================================
__device__ __forceinline__ uint32_t smem_u32(const void* p) {
    uint32_t a;
    asm("{ .reg .u64 t; cvta.to.shared.u64 t, %1; cvt.u32.u64 %0, t; }"
        : "=r"(a) : "l"(p));
    return a;
}

#define LDSM_X4(r0, r1, r2, r3, addr) \
    asm volatile("ldmatrix.sync.aligned.m8n8.x4.shared.b16 {%0,%1,%2,%3}, [%4];" \
                 : "=r"(r0), "=r"(r1), "=r"(r2), "=r"(r3) : "r"(addr))

#define MMA_BF16(c, a, b0, b1) \
    asm volatile("mma.sync.aligned.m16n8k16.row.col.f32.bf16.bf16.f32 " \
                 "{%0,%1,%2,%3}, {%4,%5,%6,%7}, {%8,%9}, {%0,%1,%2,%3};" \
                 : "+f"((c)[0]), "+f"((c)[1]), "+f"((c)[2]), "+f"((c)[3]) \
                 : "r"((a)[0]), "r"((a)[1]), "r"((a)[2]), "r"((a)[3]), \
                   "r"(b0), "r"(b1))

__device__ __forceinline__ float block_sum(float v, float* red) {
    int lane = threadIdx.x & 31, w = threadIdx.x >> 5;
    #pragma unroll
    for (int o = 16; o > 0; o >>= 1) v += __shfl_xor_sync(0xffffffffu, v, o);
    __syncthreads();
    if (lane == 0) red[w] = v;
    __syncthreads();
    if (w == 0) {
        float x = (lane < 8) ? red[lane] : 0.0f;
        #pragma unroll
        for (int o = 4; o > 0; o >>= 1) x += __shfl_xor_sync(0xffffffffu, x, o);
        if (lane == 0) red[0] = x;
    }
    __syncthreads();
    return red[0];
}
__device__ __forceinline__ float gelu_exact(float x) {
    return 0.5f * x * (1.0f + erff(x * 0.7071067811865475f));
}

// -------- weight transpose: WT[n*K+k] = W[k*N+n] --------
__global__ __launch_bounds__(256) void transpose_kernel(
    const float* __restrict__ W, float* __restrict__ WT, int K, int N)
{
    __shared__ float t[32][33];
    int n0 = blockIdx.x * 32, k0 = blockIdx.y * 32;
    int tx = threadIdx.x & 31, ty = threadIdx.x >> 5;
    #pragma unroll
    for (int i = 0; i < 4; i++)
        t[ty + 8 * i][tx] = W[(size_t)(k0 + ty + 8 * i) * N + n0 + tx];
    __syncthreads();
    #pragma unroll
    for (int i = 0; i < 4; i++)
        WT[(size_t)(n0 + ty + 8 * i) * K + k0 + tx] = t[tx][ty + 8 * i];
}

// -------- fused embedding + LN1 --------
__global__ __launch_bounds__(256) void embed_ln_kernel(
    const int* __restrict__ ids, const float* __restrict__ tok,
    const float* __restrict__ pos, const float* __restrict__ gw,
    const float* __restrict__ bw, float* __restrict__ out)
{
    __shared__ float red[32];
    int row = blockIdx.x;
    int s   = row & (SEQ - 1);
    int id  = ids[row];
    int d   = threadIdx.x * 4;
    float4 t4 = *(const float4*)(tok + (size_t)id * DM + d);
    float4 p4 = *(const float4*)(pos + (size_t)s  * DM + d);
    float4 v;
    v.x = t4.x + p4.x; v.y = t4.y + p4.y; v.z = t4.z + p4.z; v.w = t4.w + p4.w;
    float mu = block_sum(v.x + v.y + v.z + v.w, red) * (1.0f / DM);
    float dx = v.x - mu, dy = v.y - mu, dz = v.z - mu, dw = v.w - mu;
    float var = block_sum(dx*dx + dy*dy + dz*dz + dw*dw, red) * (1.0f / DM);
    float rstd = rsqrtf(var + 1e-5f);
    float4 o;
    o.x = dx * rstd * gw[d+0] + bw[d+0];
    o.y = dy * rstd * gw[d+1] + bw[d+1];
    o.z = dz * rstd * gw[d+2] + bw[d+2];
    o.w = dw * rstd * gw[d+3] + bw[d+3];
    *(float4*)(out + (size_t)row * DM + d) = o;
}

// -------- plain LN --------
__global__ __launch_bounds__(256) void ln_kernel(
    const float* __restrict__ in, const float* __restrict__ gw,
    const float* __restrict__ bw, float* __restrict__ out)
{
    __shared__ float red[32];
    int row = blockIdx.x;
    int d   = threadIdx.x * 4;
    float4 v = *(const float4*)(in + (size_t)row * DM + d);
    float mu = block_sum(v.x + v.y + v.z + v.w, red) * (1.0f / DM);
    float dx = v.x - mu, dy = v.y - mu, dz = v.z - mu, dw = v.w - mu;
    float var = block_sum(dx*dx + dy*dy + dz*dz + dw*dw, red) * (1.0f / DM);
    float rstd = rsqrtf(var + 1e-5f);
    float4 o;
    o.x = dx * rstd * gw[d+0] + bw[d+0];
    o.y = dy * rstd * gw[d+1] + bw[d+1];
    o.z = dz * rstd * gw[d+2] + bw[d+2];
    o.w = dw * rstd * gw[d+3] + bw[d+3];
    *(float4*)(out + (size_t)row * DM + d) = o;
}

// ============================================================
// bf16x3-split tensor-core GEMM (mma.sync m16n8k16)
// C[M,N] = A[M,K] * W[K,N] + bias;  W pre-transposed WT[N][K]
// CTA tile 128x128, BK=32.  epi: 0 none, 1 gelu, 2 +R
// smem tile: 128 rows x 40 bf16 (padded) = 10240 B; 4 tiles x 2 bufs
// ============================================================
#define GTILE 10240
#define GEMM_SMEM (2 * 4 * GTILE)   // 81920

__global__ __launch_bounds__(256) void gemm_bf16_kernel(
    const float* __restrict__ A, const float* __restrict__ WT,
    const float* __restrict__ bias, const float* __restrict__ R,
    float* __restrict__ C, int M, int N, int K, int epi)
{
    extern __shared__ char smem[];
    const int tid = threadIdx.x, wid = tid >> 5, lane = tid & 31;
    const int m0 = blockIdx.y * 128, n0 = blockIdx.x * 128;
    const int warpM = (wid & 3) * 32, warpN = (wid >> 2) * 64;

    float acc[2][8][4];
    #pragma unroll
    for (int i = 0; i < 2; i++)
        #pragma unroll
        for (int j = 0; j < 8; j++)
            #pragma unroll
            for (int q = 0; q < 4; q++) acc[i][j][q] = 0.0f;

    const int srow = tid >> 1, skh = (tid & 1) * 16;
    const float* Ag = A  + (size_t)(m0 + srow) * K + skh;
    const float* Bg = WT + (size_t)(n0 + srow) * K + skh;

    const uint32_t sb = smem_u32(smem);
    // per-lane ldmatrix offsets (element units within a tile)
    const int a_stat = (warpM + ((lane >> 3) & 1) * 8 + (lane & 7)) * 40 + (lane >> 4) * 8;
    const int b_stat = (warpN + ((lane >> 4) & 1) * 8 + (lane & 7)) * 40 + ((lane >> 3) & 1) * 8;
    const int s_off  = (srow * 40 + skh) * 2;   // staging byte offset

    float4 ra[4], rb[4];
    const int NKB = K >> 5;

#define LOAD_REGS(kb) { \
    _Pragma("unroll") for (int i = 0; i < 4; i++) { \
        ra[i] = *(const float4*)(Ag + (kb) * 32 + i * 4); \
        rb[i] = *(const float4*)(Bg + (kb) * 32 + i * 4); } }

#define STORE_SMEM(buf) { \
    char* base = smem + (buf) * 4 * GTILE; \
    _Pragma("unroll") for (int i = 0; i < 4; i++) { \
        float av[4] = {ra[i].x, ra[i].y, ra[i].z, ra[i].w}; \
        float bv[4] = {rb[i].x, rb[i].y, rb[i].z, rb[i].w}; \
        _Pragma("unroll") for (int j = 0; j < 2; j++) { \
            int off = s_off + (i * 4 + 2 * j) * 2; \
            float x0 = av[2*j], x1 = av[2*j+1]; \
            __nv_bfloat162 h2 = __floats2bfloat162_rn(x0, x1); \
            __nv_bfloat162 l2 = __floats2bfloat162_rn( \
                x0 - __bfloat162float(h2.x), x1 - __bfloat162float(h2.y)); \
            *(uint32_t*)(base + off)             = *(uint32_t*)&h2; \
            *(uint32_t*)(base + GTILE + off)     = *(uint32_t*)&l2; \
            x0 = bv[2*j]; x1 = bv[2*j+1]; \
            h2 = __floats2bfloat162_rn(x0, x1); \
            l2 = __floats2bfloat162_rn( \
                x0 - __bfloat162float(h2.x), x1 - __bfloat162float(h2.y)); \
            *(uint32_t*)(base + 2 * GTILE + off) = *(uint32_t*)&h2; \
            *(uint32_t*)(base + 3 * GTILE + off) = *(uint32_t*)&l2; \
        } } }

#define COMPUTE(buf) { \
    uint32_t tb0 = sb + (buf) * 4 * GTILE; \
    _Pragma("unroll") for (int ks = 0; ks < 2; ks++) { \
        const int Cc = ks * 16; \
        uint32_t fa[2][4], fl[2][4], bh[4][4], bl[4][4]; \
        _Pragma("unroll") for (int mb = 0; mb < 2; mb++) { \
            uint32_t ad = tb0 + (uint32_t)(a_stat + mb * 640 + Cc) * 2; \
            LDSM_X4(fa[mb][0], fa[mb][1], fa[mb][2], fa[mb][3], ad); \
            LDSM_X4(fl[mb][0], fl[mb][1], fl[mb][2], fl[mb][3], ad + GTILE); \
        } \
        _Pragma("unroll") for (int p = 0; p < 4; p++) { \
            uint32_t bd = tb0 + 2 * GTILE + (uint32_t)(b_stat + p * 640 + Cc) * 2; \
            LDSM_X4(bh[p][0], bh[p][1], bh[p][2], bh[p][3], bd); \
            LDSM_X4(bl[p][0], bl[p][1], bl[p][2], bl[p][3], bd + GTILE); \
        } \
        _Pragma("unroll") for (int mb = 0; mb < 2; mb++) \
        _Pragma("unroll") for (int nb = 0; nb < 8; nb++) { \
            const int p = nb >> 1, q = (nb & 1) * 2; \
            MMA_BF16(acc[mb][nb], fa[mb], bh[p][q], bh[p][q + 1]); \
            MMA_BF16(acc[mb][nb], fa[mb], bl[p][q], bl[p][q + 1]); \
            MMA_BF16(acc[mb][nb], fl[mb], bh[p][q], bh[p][q + 1]); \
        } } }

    LOAD_REGS(0);
    STORE_SMEM(0);
    __syncthreads();

    for (int kb = 0; kb < NKB; kb++) {
        if (kb + 1 < NKB) LOAD_REGS(kb + 1);
        COMPUTE(kb & 1);
        if (kb + 1 < NKB) {
            __syncthreads();
            STORE_SMEM((kb + 1) & 1);
            __syncthreads();
        }
    }

    // epilogue
    const int g = lane >> 2, t = lane & 3;
    #pragma unroll
    for (int mb = 0; mb < 2; mb++)
        #pragma unroll
        for (int nb = 0; nb < 8; nb++) {
            int row = m0 + warpM + mb * 16 + g;
            int col = n0 + warpN + nb * 8 + 2 * t;
            float2 b2 = *(const float2*)(bias + col);
            float v0 = acc[mb][nb][0] + b2.x, v1 = acc[mb][nb][1] + b2.y;
            float v2 = acc[mb][nb][2] + b2.x, v3 = acc[mb][nb][3] + b2.y;
            if (epi == 1) {
                v0 = gelu_exact(v0); v1 = gelu_exact(v1);
                v2 = gelu_exact(v2); v3 = gelu_exact(v3);
            } else if (epi == 2) {
                float2 r0 = *(const float2*)(R + (size_t)row * N + col);
                float2 r1 = *(const float2*)(R + (size_t)(row + 8) * N + col);
                v0 += r0.x; v1 += r0.y; v2 += r1.x; v3 += r1.y;
            }
            float2 o0 = {v0, v1}, o1 = {v2, v3};
            *(float2*)(C + (size_t)row * N + col) = o0;
            *(float2*)(C + (size_t)(row + 8) * N + col) = o1;
        }
}

// -------- flash attention (fp32, BQ=BK=64, online softmax) --------
__global__ __launch_bounds__(256) void flash_kernel(
    const float* __restrict__ Qg, const float* __restrict__ Kg,
    const float* __restrict__ Vg, const int* __restrict__ ids,
    float* __restrict__ Og, int causal)
{
    extern __shared__ float sm[];
    float* Qs = sm;                 // [d][q]  64x64
    float* Ks = sm + 4096;          // [d][c]  64x64
    float* Vs = sm + 8192;          // [k][d]  64x64
    float* Ps = sm + 12288;         // [q][65]
    int*   sid = (int*)(sm + 12288 + 64 * 65);

    const int tid = threadIdx.x;
    const int tx = tid & 15, ty = tid >> 4;
    const int qt = blockIdx.x, h = blockIdx.y, b = blockIdx.z;
    const int qbase = qt * 64;
    const float* Qp = Qg + (size_t)b * SEQ * DM + h * DHEAD;
    const float* Kp = Kg + (size_t)b * SEQ * DM + h * DHEAD;
    const float* Vp = Vg + (size_t)b * SEQ * DM + h * DHEAD;

    {
        int r = tid >> 2, dseg = (tid & 3) * 16;
        const float* gp = Qp + (size_t)(qbase + r) * DM + dseg;
        #pragma unroll
        for (int u = 0; u < 4; u++) {
            float4 q4 = *(const float4*)(gp + u * 4);
            Qs[(dseg + u*4 + 0) * 64 + r] = q4.x;
            Qs[(dseg + u*4 + 1) * 64 + r] = q4.y;
            Qs[(dseg + u*4 + 2) * 64 + r] = q4.z;
            Qs[(dseg + u*4 + 3) * 64 + r] = q4.w;
        }
    }

    float m[4], l[4], acc[4][4];
    #pragma unroll
    for (int i = 0; i < 4; i++) {
        m[i] = -3.0e38f; l[i] = 0.0f;
        #pragma unroll
        for (int j = 0; j < 4; j++) acc[i][j] = 0.0f;
    }

    const int nkt = causal ? (qt + 1) : (SEQ / 64);
    for (int kt = 0; kt < nkt; kt++) {
        const int kbase = kt * 64;
        {
            int r = tid >> 2, dseg = (tid & 3) * 16;
            const float* kp = Kp + (size_t)(kbase + r) * DM + dseg;
            const float* vp = Vp + (size_t)(kbase + r) * DM + dseg;
            #pragma unroll
            for (int u = 0; u < 4; u++) {
                float4 k4 = *(const float4*)(kp + u * 4);
                Ks[(dseg + u*4 + 0) * 64 + r] = k4.x;
                Ks[(dseg + u*4 + 1) * 64 + r] = k4.y;
                Ks[(dseg + u*4 + 2) * 64 + r] = k4.z;
                Ks[(dseg + u*4 + 3) * 64 + r] = k4.w;
                *(float4*)&Vs[r * 64 + dseg + u * 4] = *(const float4*)(vp + u * 4);
            }
            if (tid < 64) sid[tid] = ids[b * SEQ + kbase + tid];
        }
        __syncthreads();

        float sc[4][4];
        #pragma unroll
        for (int i = 0; i < 4; i++)
            #pragma unroll
            for (int j = 0; j < 4; j++) sc[i][j] = 0.0f;
        #pragma unroll 8
        for (int d = 0; d < 64; d++) {
            float4 q4 = *(float4*)&Qs[d * 64 + ty * 4];
            float4 k4 = *(float4*)&Ks[d * 64 + tx * 4];
            float qa[4] = {q4.x, q4.y, q4.z, q4.w};
            float ka[4] = {k4.x, k4.y, k4.z, k4.w};
            #pragma unroll
            for (int i = 0; i < 4; i++)
                #pragma unroll
                for (int j = 0; j < 4; j++) sc[i][j] += qa[i] * ka[j];
        }

        #pragma unroll
        for (int i = 0; i < 4; i++) {
            int qrow = qbase + ty * 4 + i;
            float rowmax = -3.0e38f;
            #pragma unroll
            for (int j = 0; j < 4; j++) {
                float v = sc[i][j] * 0.125f;
                int kc = kbase + tx * 4 + j;
                if (causal && kc > qrow) v += NEGV;
                if (sid[tx * 4 + j] == 0) v += NEGV;
                sc[i][j] = v;
                rowmax = fmaxf(rowmax, v);
            }
            #pragma unroll
            for (int o = 8; o > 0; o >>= 1)
                rowmax = fmaxf(rowmax, __shfl_xor_sync(0xffffffffu, rowmax, o));
            float mnew  = fmaxf(m[i], rowmax);
            float alpha = __expf(m[i] - mnew);
            float rs = 0.0f;
            #pragma unroll
            for (int j = 0; j < 4; j++) {
                float p = __expf(sc[i][j] - mnew);
                Ps[(ty * 4 + i) * 65 + tx * 4 + j] = p;
                rs += p;
            }
            #pragma unroll
            for (int o = 8; o > 0; o >>= 1)
                rs += __shfl_xor_sync(0xffffffffu, rs, o);
            l[i] = l[i] * alpha + rs;
            m[i] = mnew;
            #pragma unroll
            for (int j = 0; j < 4; j++) acc[i][j] *= alpha;
        }
        __syncthreads();

        #pragma unroll 4
        for (int kk = 0; kk < 64; kk++) {
            float4 v4 = *(float4*)&Vs[kk * 64 + tx * 4];
            #pragma unroll
            for (int i = 0; i < 4; i++) {
                float p = Ps[(ty * 4 + i) * 65 + kk];
                acc[i][0] += p * v4.x; acc[i][1] += p * v4.y;
                acc[i][2] += p * v4.z; acc[i][3] += p * v4.w;
            }
        }
        __syncthreads();
    }

    #pragma unroll
    for (int i = 0; i < 4; i++) {
        float inv = 1.0f / l[i];
        float4 o;
        o.x = acc[i][0] * inv; o.y = acc[i][1] * inv;
        o.z = acc[i][2] * inv; o.w = acc[i][3] * inv;
        size_t off = ((size_t)b * SEQ + qbase + ty * 4 + i) * DM + h * DHEAD + tx * 4;
        *(float4*)(Og + off) = o;
    }
}

// ============================================================
// host pipeline
// ============================================================
extern "C" void kernel_launch(void* const* d_in, const int* in_sizes, int n_in,
                              void* d_out, int out_size)
{
    const float* input_embedding = (const float*)d_in[0];
    const int*   input_ids       = (const int*)  d_in[1];
    const int*   target_ids      = (const int*)  d_in[2];
    const float* tok_emb = (const float*)d_in[3];
    const float* pos_emb = (const float*)d_in[4];
    const float* ln1_g = (const float*)d_in[5],  *ln1_b = (const float*)d_in[6];
    const float* q1_w  = (const float*)d_in[7],  *q1_b  = (const float*)d_in[8];
    const float* k1_w  = (const float*)d_in[9],  *k1_b  = (const float*)d_in[10];
    const float* v1_w  = (const float*)d_in[11], *v1_b  = (const float*)d_in[12];
    const float* out1_w= (const float*)d_in[13], *out1_b= (const float*)d_in[14];
    const float* ln2_g = (const float*)d_in[15], *ln2_b = (const float*)d_in[16];
    const float* q2_w  = (const float*)d_in[17], *q2_b  = (const float*)d_in[18];
    const float* k2_w  = (const float*)d_in[19], *k2_b  = (const float*)d_in[20];
    const float* v2_w  = (const float*)d_in[21], *v2_b  = (const float*)d_in[22];
    const float* out2_w= (const float*)d_in[23], *out2_b= (const float*)d_in[24];
    const float* ln3_g = (const float*)d_in[25], *ln3_b = (const float*)d_in[26];
    const float* mlp_w1= (const float*)d_in[27], *mlp_b1= (const float*)d_in[28];
    const float* mlp_w2= (const float*)d_in[29], *mlp_b2= (const float*)d_in[30];

    float *xln, *qb, *kb, *vb, *ab, *hb, *rb, *zb, *tb, *wt;
    cudaGetSymbolAddress((void**)&xln, g_xln);
    cudaGetSymbolAddress((void**)&qb,  g_qb);
    cudaGetSymbolAddress((void**)&kb,  g_kb);
    cudaGetSymbolAddress((void**)&vb,  g_vb);
    cudaGetSymbolAddress((void**)&ab,  g_ab);
    cudaGetSymbolAddress((void**)&hb,  g_hb);
    cudaGetSymbolAddress((void**)&rb,  g_rb);
    cudaGetSymbolAddress((void**)&zb,  g_zb);
    cudaGetSymbolAddress((void**)&tb,  g_tb);
    cudaGetSymbolAddress((void**)&wt,  g_wt);

    const int FLASH_SMEM = (4096 * 3 + 64 * 65) * 4 + 64 * 4;   // 66048 B
    cudaFuncSetAttribute(flash_kernel,
                         cudaFuncAttributeMaxDynamicSharedMemorySize, FLASH_SMEM);
    cudaFuncSetAttribute(gemm_bf16_kernel,
                         cudaFuncAttributeMaxDynamicSharedMemorySize, GEMM_SMEM);

    // ---- transpose all weights into [N][K] scratch ----
    {
        dim3 g1(DM / 32, DM / 32);
        transpose_kernel<<<g1, 256>>>(q1_w,  wt + WT_Q1, DM, DM);
        transpose_kernel<<<g1, 256>>>(k1_w,  wt + WT_K1, DM, DM);
        transpose_kernel<<<g1, 256>>>(v1_w,  wt + WT_V1, DM, DM);
        transpose_kernel<<<g1, 256>>>(out1_w,wt + WT_O1, DM, DM);
        transpose_kernel<<<g1, 256>>>(q2_w,  wt + WT_Q2, DM, DM);
        transpose_kernel<<<g1, 256>>>(k2_w,  wt + WT_K2, DM, DM);
        transpose_kernel<<<g1, 256>>>(v2_w,  wt + WT_V2, DM, DM);
        transpose_kernel<<<g1, 256>>>(out2_w,wt + WT_O2, DM, DM);
        dim3 gm1(4 * DM / 32, DM / 32);
        transpose_kernel<<<gm1, 256>>>(mlp_w1, wt + WT_M1, DM, 4 * DM);
        dim3 gm2(DM / 32, 4 * DM / 32);
        transpose_kernel<<<gm2, 256>>>(mlp_w2, wt + WT_M2, 4 * DM, DM);
    }

    dim3 gN1(DM / 128, MTOK / 128);          // (8, 32)
    dim3 gN4(4 * DM / 128, MTOK / 128);      // (32, 32)
    dim3 gF(SEQ / 64, NH, BATCH);

    // x = LN1(tok_emb[tgt] + pos)
    embed_ln_kernel<<<MTOK, 256>>>(target_ids, tok_emb, pos_emb, ln1_g, ln1_b, xln);

    // self-attention
    gemm_bf16_kernel<<<gN1, 256, GEMM_SMEM>>>(xln, wt + WT_Q1, q1_b, nullptr, qb, MTOK, DM, DM, 0);
    gemm_bf16_kernel<<<gN1, 256, GEMM_SMEM>>>(xln, wt + WT_K1, k1_b, nullptr, kb, MTOK, DM, DM, 0);
    gemm_bf16_kernel<<<gN1, 256, GEMM_SMEM>>>(xln, wt + WT_V1, v1_b, nullptr, vb, MTOK, DM, DM, 0);
    flash_kernel<<<gF, 256, FLASH_SMEM>>>(qb, kb, vb, target_ids, ab, 1);
    gemm_bf16_kernel<<<gN1, 256, GEMM_SMEM>>>(ab, wt + WT_O1, out1_b, xln, hb, MTOK, DM, DM, 2);

    // cross-attention (residual uses LN2 output, matching reference)
    ln_kernel<<<MTOK, 256>>>(hb, ln2_g, ln2_b, zb);
    gemm_bf16_kernel<<<gN1, 256, GEMM_SMEM>>>(zb, wt + WT_Q2, q2_b, nullptr, qb, MTOK, DM, DM, 0);
    gemm_bf16_kernel<<<gN1, 256, GEMM_SMEM>>>(input_embedding, wt + WT_K2, k2_b, nullptr, kb, MTOK, DM, DM, 0);
    gemm_bf16_kernel<<<gN1, 256, GEMM_SMEM>>>(input_embedding, wt + WT_V2, v2_b, nullptr, vb, MTOK, DM, DM, 0);
    flash_kernel<<<gF, 256, FLASH_SMEM>>>(qb, kb, vb, input_ids, ab, 0);
    gemm_bf16_kernel<<<gN1, 256, GEMM_SMEM>>>(ab, wt + WT_O2, out2_b, zb, rb, MTOK, DM, DM, 2);

    // MLP
    ln_kernel<<<MTOK, 256>>>(rb, ln3_g, ln3_b, zb);
    gemm_bf16_kernel<<<gN4, 256, GEMM_SMEM>>>(zb, wt + WT_M1, mlp_b1, nullptr, tb, MTOK, 4 * DM, DM, 1);
    gemm_bf16_kernel<<<gN1, 256, GEMM_SMEM>>>(tb, wt + WT_M2, mlp_b2, rb, (float*)d_out, MTOK, DM, 4 * DM, 2);
}